// round 6
// baseline (speedup 1.0000x reference)
#include <cuda_runtime.h>
#include <cstdint>

// Problem shape (fixed)
#define EXPERTS 16
#define MTOK    2048
#define DIM     1024
#define HID     4096

// GEMM tiling
#define BM 128
#define BN 128
#define BK 32
#define PANEL 4096                      // floats per 128x32 pair-packed swizzled panel (16KB)
#define STG   (2*PANEL)                 // A panel + B panel per stage
#define SMEM_BYTES (3*STG*4)            // 98304 B -> 2 CTAs/SM

// Scratch (allocation-free rule: __device__ globals)
__device__ float g_xp [(size_t)EXPERTS*MTOK*DIM];   // x panels   [e][mb=16][kb=32]
__device__ float g_w1p[(size_t)EXPERTS*DIM*HID];    // w1^T panels [e][nb=32][kb=32]
__device__ float g_w2p[(size_t)EXPERTS*HID*DIM];    // w2^T panels [e][nb=8][kb=128]
__device__ float g_hid[(size_t)EXPERTS*MTOK*HID];   // hidden panels [e][mb=16][kb=128]

// ---------------- helpers ----------------
__device__ __forceinline__ float cvt_rna_f(float x){
    unsigned u; asm("cvt.rna.tf32.f32 %0, %1;" : "=r"(u) : "f"(x)); return __uint_as_float(u);
}
__device__ __forceinline__ float gelu_exact(float x){
    return 0.5f*x*(1.0f+erff(x*0.70710678118654752440f));
}
__device__ __forceinline__ void cp16(void* smem, const void* gmem){
    unsigned s = (unsigned)__cvta_generic_to_shared(smem);
    asm volatile("cp.async.cg.shared.global [%0], [%1], 16;\n" :: "r"(s), "l"(gmem));
}

// Pair-packed panel layout (both A and B): 128 rows x 32 k, 16KB.
// Pair j=0..15 -> (k0, k0+4) with k0 = 8*(j>>2) + (j&3); float2 at byte
// off = row*128 + j*8, swizzled: off ^ ((row&7)*16)  [j*8 term never reaches the XOR bits].

// ---------------- pre-pass: x -> rounded pair-packed panels ----------------
__global__ __launch_bounds__(256) void pack_x(const float* __restrict__ X, float* __restrict__ P){
    const int e = blockIdx.z, mb = blockIdx.y, kb = blockIdx.x;   // 128 rows x 32 k
    char* panel = (char*)(P + (((size_t)e*16 + mb)*(DIM/32) + kb)*(size_t)PANEL);
    #pragma unroll
    for (int i=0;i<4;i++){
        int idx = threadIdx.x + i*256;       // 1024 float4
        int m = idx>>3, k4 = idx&7;
        float4 v = *(const float4*)(X + ((size_t)e*MTOK + (size_t)mb*128 + m)*DIM + kb*32 + k4*4);
        float f[4] = {cvt_rna_f(v.x), cvt_rna_f(v.y), cvt_rna_f(v.z), cvt_rna_f(v.w)};
        int c = k4>>1, elem = k4&1;
        uint32_t sxor = (uint32_t)((m&7)*16);
        #pragma unroll
        for (int tt=0; tt<4; tt++){
            uint32_t off = (uint32_t)(m*128) + ((uint32_t)((c*4+tt)*8 + elem*4) ^ sxor);
            *(float*)(panel + off) = f[tt];
        }
    }
}

// ---- pre-pass: W[K,N] -> rounded W^T pair-packed panels [e][nb][kb] ----
__global__ __launch_bounds__(256) void pack_w(const float* __restrict__ W, float* __restrict__ P,
                                              int K, int N){
    __shared__ float ts[32][133];
    const int e = blockIdx.z, nb = blockIdx.x, kb = blockIdx.y;
    const float* src = W + ((size_t)e*K + (size_t)kb*32)*N + (size_t)nb*128;
    #pragma unroll
    for (int i=0;i<16;i++){
        int idx = threadIdx.x + i*256;
        int r = idx>>7, c = idx&127;
        ts[r][c] = src[(size_t)r*N + c];
    }
    __syncthreads();
    char* panel = (char*)(P + (((size_t)e*(N>>7) + nb)*(size_t)(K>>5) + kb)*(size_t)PANEL);
    #pragma unroll
    for (int i=0;i<8;i++){
        int idx = threadIdx.x + i*256;
        int n = idx>>4, j = idx&15;
        int k0 = ((j>>2)<<3) + (j&3);
        float2 v = make_float2(cvt_rna_f(ts[k0][n]), cvt_rna_f(ts[k0+4][n]));
        uint32_t off = (uint32_t)(n*128 + j*8);
        off ^= (off>>3)&0x70;
        *(float2*)(panel + off) = v;
    }
}

// ---------------- main GEMM: mma.sync tf32, double-buffered fragments ----------------
// A panels [e][mb][kb], B panels [e][nb][kb]; both 128x32 pair-packed swizzled.
template<bool G1>
__global__ void __launch_bounds__(256,2)
gemm_t(const float* __restrict__ Ap, const float* __restrict__ Bp,
       const float* __restrict__ bias, float* __restrict__ Out, int KT)
{
    extern __shared__ float sm[];
    const int tid = threadIdx.x, warp = tid>>5, lane = tid&31;
    const int g = lane>>2, t = lane&3;
    const int wm = (warp&3)*32, wn = (warp>>2)*64;
    const int bx = blockIdx.x, by = blockIdx.y, e = blockIdx.z;
    const int NB = gridDim.x;

    const float* Ab0 = Ap + ((size_t)e*gridDim.y + by)*(size_t)KT*PANEL;
    const float* Bb0 = Bp + ((size_t)e*NB + bx)*(size_t)KT*PANEL;

    auto loadStage = [&](int slot, int s){
        float* dst = sm + slot*STG;
        const float* a = Ab0 + (size_t)s*PANEL;
        const float* b = Bb0 + (size_t)s*PANEL;
        #pragma unroll
        for (int j=0;j<4;j++){ int idx = tid + j*256; cp16(dst + idx*4, a + idx*4); }
        #pragma unroll
        for (int j=0;j<4;j++){ int idx = tid + j*256; cp16(dst + PANEL + idx*4, b + idx*4); }
    };

    // frag byte offsets
    const uint32_t axor = (uint32_t)(g*16);
    uint32_t aoff[2][2], boff[8];
    #pragma unroll
    for (int im=0;im<2;im++){
        aoff[im][0] = (uint32_t)((wm + im*16 + g    )*128);
        aoff[im][1] = (uint32_t)((wm + im*16 + g + 8)*128);
    }
    #pragma unroll
    for (int in=0;in<8;in++) boff[in] = (uint32_t)((wn + in*8 + g)*128);

    float c[2][8][4];
    #pragma unroll
    for (int im=0;im<2;im++)
        #pragma unroll
        for (int in=0;in<8;in++)
            #pragma unroll
            for (int r=0;r<4;r++) c[im][in][r]=0.0f;

    uint32_t aF[2][2][4], bF[2][8][2];
    auto ldA = [&](const char* Ac, int ck, uint32_t (&a)[2][4]){
        uint32_t ko = (uint32_t)(ck*32 + t*8) ^ axor;
        #pragma unroll
        for (int im=0;im<2;im++){
            float2 v0 = *(const float2*)(Ac + aoff[im][0] + ko);
            float2 v1 = *(const float2*)(Ac + aoff[im][1] + ko);
            a[im][0]=__float_as_uint(v0.x); a[im][2]=__float_as_uint(v0.y);
            a[im][1]=__float_as_uint(v1.x); a[im][3]=__float_as_uint(v1.y);
        }
    };
    auto ldB = [&](const char* Bc, int ck, uint32_t (&b)[8][2]){
        uint32_t ko = (uint32_t)(ck*32 + t*8) ^ axor;
        #pragma unroll
        for (int in=0;in<8;in++){
            float2 v = *(const float2*)(Bc + boff[in] + ko);
            b[in][0]=__float_as_uint(v.x); b[in][1]=__float_as_uint(v.y);
        }
    };

    loadStage(0,0); asm volatile("cp.async.commit_group;\n");
    loadStage(1,1); asm volatile("cp.async.commit_group;\n");

    #pragma unroll 1
    for (int s=0; s<KT; s++){
        asm volatile("cp.async.wait_group 1;\n");
        __syncthreads();
        if (s+2 < KT) loadStage((s+2)%3, s+2);
        asm volatile("cp.async.commit_group;\n");   // always commit -> exact accounting

        const char* Ac = (const char*)(sm + (s%3)*STG);
        const char* Bc = Ac + PANEL*4;

        ldA(Ac, 0, aF[0]); ldB(Bc, 0, bF[0]);
        #pragma unroll
        for (int ck=0; ck<4; ck++){
            if (ck < 3){ ldA(Ac, ck+1, aF[(ck+1)&1]); ldB(Bc, ck+1, bF[(ck+1)&1]); }
            uint32_t (&a)[2][4] = aF[ck&1];
            uint32_t (&b)[8][2] = bF[ck&1];
            #pragma unroll
            for (int im=0;im<2;im++)
                #pragma unroll
                for (int in=0;in<8;in++){
                    asm volatile(
                        "mma.sync.aligned.m16n8k8.row.col.f32.tf32.tf32.f32 "
                        "{%0,%1,%2,%3}, {%4,%5,%6,%7}, {%8,%9}, {%0,%1,%2,%3};"
                        : "+f"(c[im][in][0]), "+f"(c[im][in][1]),
                          "+f"(c[im][in][2]), "+f"(c[im][in][3])
                        : "r"(a[im][0]), "r"(a[im][1]), "r"(a[im][2]), "r"(a[im][3]),
                          "r"(b[in][0]), "r"(b[in][1]));
                }
        }
    }
    asm volatile("cp.async.wait_group 0;\n");

    if (G1){
        // stage bias+gelu+round through smem, emit hidden as pair-packed panels
        __syncthreads();                       // all warps done reading pipeline smem
        float* stage = sm;                     // [128][132]
        #pragma unroll
        for (int im=0;im<2;im++)
            #pragma unroll
            for (int rh=0;rh<2;rh++){
                int row = wm + im*16 + g + rh*8;
                #pragma unroll
                for (int in=0;in<8;in++){
                    int col = wn + in*8 + 2*t;
                    float v0 = c[im][in][rh*2+0] + __ldg(&bias[bx*BN+col]);
                    float v1 = c[im][in][rh*2+1] + __ldg(&bias[bx*BN+col+1]);
                    v0 = cvt_rna_f(gelu_exact(v0));
                    v1 = cvt_rna_f(gelu_exact(v1));
                    *(float2*)&stage[row*132 + col] = make_float2(v0, v1);
                }
            }
        __syncthreads();
        // pack: 8192 pairs -> 4 panels (k-blocks bx*4 .. bx*4+3)
        const int KT2 = HID/32;
        #pragma unroll
        for (int i=0;i<32;i++){
            int p = tid + i*256;
            int m = p>>6, r = p&63;
            int kbl = r>>4, j = r&15;
            int k0 = kbl*32 + ((j>>2)<<3) + (j&3);
            float2 v = make_float2(stage[m*132 + k0], stage[m*132 + k0 + 4]);
            char* panel = (char*)(Out + (((size_t)e*16 + by)*KT2 + (bx*4 + kbl))*(size_t)PANEL);
            uint32_t off = (uint32_t)(m*128) + ((uint32_t)(j*8) ^ (uint32_t)((m&7)*16));
            *(float2*)(panel + off) = v;
        }
    } else {
        const int Nout = NB*BN;
        #pragma unroll
        for (int im=0;im<2;im++)
            #pragma unroll
            for (int rh=0;rh<2;rh++){
                int row = by*BM + wm + im*16 + g + rh*8;
                #pragma unroll
                for (int in=0;in<8;in++){
                    int col = bx*BN + wn + in*8 + 2*t;
                    float v0 = c[im][in][rh*2+0] + __ldg(&bias[col]);
                    float v1 = c[im][in][rh*2+1] + __ldg(&bias[col+1]);
                    *reinterpret_cast<float2*>(&Out[((size_t)e*MTOK + row)*Nout + col]) =
                        make_float2(v0, v1);
                }
            }
    }
}

// ---------------- host ----------------
extern "C" void kernel_launch(void* const* d_in, const int* in_sizes, int n_in,
                              void* d_out, int out_size)
{
    const float* x  = (const float*)d_in[0];   // [E, 2048, 1024]
    const float* w1 = (const float*)d_in[1];   // [E, 1024, 4096]
    const float* w2 = (const float*)d_in[2];   // [E, 4096, 1024]
    const float* b1 = (const float*)d_in[3];   // [4096]
    const float* b2 = (const float*)d_in[4];   // [1024]
    float* out = (float*)d_out;                // [E, 2048, 1024]

    float *xp, *w1p, *w2p, *hid;
    cudaGetSymbolAddress((void**)&xp,  g_xp);
    cudaGetSymbolAddress((void**)&w1p, g_w1p);
    cudaGetSymbolAddress((void**)&w2p, g_w2p);
    cudaGetSymbolAddress((void**)&hid, g_hid);

    cudaFuncSetAttribute(gemm_t<true>,  cudaFuncAttributeMaxDynamicSharedMemorySize, SMEM_BYTES);
    cudaFuncSetAttribute(gemm_t<false>, cudaFuncAttributeMaxDynamicSharedMemorySize, SMEM_BYTES);

    // pre-pass: rounding + panelization (x and both weights)
    pack_x<<<dim3(DIM/32, MTOK/128, EXPERTS), 256>>>(x, xp);
    pack_w<<<dim3(HID/128, DIM/32, EXPERTS), 256>>>(w1, w1p, DIM, HID);
    pack_w<<<dim3(DIM/128, HID/32, EXPERTS), 256>>>(w2, w2p, HID, DIM);

    // GEMM1 + exact GELU -> hidden panels; GEMM2 -> row-major out
    gemm_t<true ><<<dim3(HID/BN, MTOK/BM, EXPERTS), 256, SMEM_BYTES>>>(xp, w1p, b1, hid, DIM/32);
    gemm_t<false><<<dim3(DIM/BN, MTOK/BM, EXPERTS), 256, SMEM_BYTES>>>(hid, w2p, b2, out, HID/32);
}

// round 7
// speedup vs baseline: 1.8477x; 1.8477x over previous
#include <cuda_runtime.h>
#include <cuda_fp16.h>
#include <cstdint>

// Problem shape (fixed)
#define EXPERTS 16
#define MTOK    2048
#define DIM     1024
#define HID     4096

// GEMM tiling
#define BM 128
#define BN 128
#define BK 64                            // fp16: 64 k per 16KB panel (128B rows)
#define PANELH 8192                      // halfs per 128x64 pair-packed swizzled panel (16KB)
#define STG_B  (2*PANELH*2)              // A panel + B panel bytes per stage (32KB)
#define SMEM_BYTES (3*STG_B)             // 98304 -> 2 CTAs/SM

// Scratch (allocation-free rule: __device__ globals)
__device__ __half g_xp [(size_t)EXPERTS*MTOK*DIM];   // x panels    [e][mb=16][kb=16]
__device__ __half g_w1p[(size_t)EXPERTS*DIM*HID];    // w1^T panels [e][nb=32][kb=16]
__device__ __half g_w2p[(size_t)EXPERTS*HID*DIM];    // w2^T panels [e][nb=8][kb=64]
__device__ __half g_hid[(size_t)EXPERTS*MTOK*HID];   // hidden panels [e][mb=16][kb=64]

// ---------------- helpers ----------------
__device__ __forceinline__ float gelu_exact(float x){
    return 0.5f*x*(1.0f+erff(x*0.70710678118654752440f));
}
__device__ __forceinline__ void cp16(void* smem, const void* gmem){
    unsigned s = (unsigned)__cvta_generic_to_shared(smem);
    asm volatile("cp.async.cg.shared.global [%0], [%1], 16;\n" :: "r"(s), "l"(gmem));
}
__device__ __forceinline__ uint32_t h2u(float a, float b){
    __half2 h = __floats2half2_rn(a, b);
    return *reinterpret_cast<uint32_t*>(&h);
}

// Pair-packed fp16 panel: 128 rows x 64 k, 16KB. For k16 chunk c (0..3), pair
// j = c*4+t holds {k=c*16+2t, +1} (lo b32) and {k=c*16+2t+8, +9} (hi b32):
// byte off = row*128 + j*8, swizzled off ^ ((row&7)*16).

// ---------------- pre-pass: x -> fp16 pair-packed panels ----------------
__global__ __launch_bounds__(256) void pack_x(const float* __restrict__ X, __half* __restrict__ P){
    __shared__ float xs[128][68];
    const int e = blockIdx.z, mb = blockIdx.y, kb = blockIdx.x;   // 128 rows x 64 k
    const float* src = X + ((size_t)e*MTOK + (size_t)mb*128)*DIM + kb*64;
    #pragma unroll
    for (int i=0;i<8;i++){
        int idx = threadIdx.x + i*256;      // 2048 float4
        int m = idx>>4, c4 = idx&15;
        float4 v = *(const float4*)(src + (size_t)m*DIM + c4*4);
        xs[m][c4*4+0]=v.x; xs[m][c4*4+1]=v.y; xs[m][c4*4+2]=v.z; xs[m][c4*4+3]=v.w;
    }
    __syncthreads();
    char* panel = (char*)(P + (((size_t)e*16 + mb)*(DIM/64) + kb)*(size_t)PANELH);
    #pragma unroll
    for (int i=0;i<8;i++){
        int p = threadIdx.x + i*256;        // 2048 pairs
        int m = p>>4, j = p&15;
        int k0 = (j>>2)*16 + (j&3)*2;
        uint2 v = make_uint2(h2u(xs[m][k0],   xs[m][k0+1]),
                             h2u(xs[m][k0+8], xs[m][k0+9]));
        uint32_t off = (uint32_t)(m*128 + j*8);
        off ^= (uint32_t)((m&7)*16);
        *(uint2*)(panel + off) = v;
    }
}

// ---- pre-pass: W[K,N] -> fp16 W^T pair-packed panels [e][nb][kb] ----
__global__ __launch_bounds__(256) void pack_w(const float* __restrict__ W, __half* __restrict__ P,
                                              int K, int N){
    __shared__ float ts[64][132];
    const int e = blockIdx.z, nb = blockIdx.x, kb = blockIdx.y;   // 64 k x 128 n
    const float* src = W + ((size_t)e*K + (size_t)kb*64)*N + (size_t)nb*128;
    #pragma unroll
    for (int i=0;i<8;i++){
        int idx = threadIdx.x + i*256;      // 2048 float4
        int r = idx>>5, c4 = idx&31;
        float4 v = *(const float4*)(src + (size_t)r*N + c4*4);
        ts[r][c4*4+0]=v.x; ts[r][c4*4+1]=v.y; ts[r][c4*4+2]=v.z; ts[r][c4*4+3]=v.w;
    }
    __syncthreads();
    char* panel = (char*)(P + (((size_t)e*(N>>7) + nb)*(size_t)(K>>6) + kb)*(size_t)PANELH);
    #pragma unroll
    for (int i=0;i<8;i++){
        int p = threadIdx.x + i*256;        // 2048 pairs
        int n = p>>4, j = p&15;
        int k0 = (j>>2)*16 + (j&3)*2;
        uint2 v = make_uint2(h2u(ts[k0][n],   ts[k0+1][n]),
                             h2u(ts[k0+8][n], ts[k0+9][n]));
        uint32_t off = (uint32_t)(n*128 + j*8);
        off ^= (uint32_t)((n&7)*16);
        *(uint2*)(panel + off) = v;
    }
}

// ---------------- main GEMM: mma.sync fp16 m16n8k16, fp32 accum ----------------
template<bool G1>
__global__ void __launch_bounds__(256,2)
gemm_t(const __half* __restrict__ Ap, const __half* __restrict__ Bp,
       const float* __restrict__ bias, void* __restrict__ OutV, int KT)
{
    extern __shared__ float sm[];
    const int tid = threadIdx.x, warp = tid>>5, lane = tid&31;
    const int g = lane>>2, t = lane&3;
    const int wm = (warp&3)*32, wn = (warp>>2)*64;
    const int bx = blockIdx.x, by = blockIdx.y, e = blockIdx.z;
    const int NB = gridDim.x;

    const __half* Ab0 = Ap + ((size_t)e*gridDim.y + by)*(size_t)KT*PANELH;
    const __half* Bb0 = Bp + ((size_t)e*NB + bx)*(size_t)KT*PANELH;

    auto loadStage = [&](int slot, int s){
        char* dst = (char*)sm + slot*STG_B;
        const char* a = (const char*)(Ab0 + (size_t)s*PANELH);
        const char* b = (const char*)(Bb0 + (size_t)s*PANELH);
        #pragma unroll
        for (int j=0;j<4;j++){ int idx = tid + j*256; cp16(dst + idx*16, a + idx*16); }
        #pragma unroll
        for (int j=0;j<4;j++){ int idx = tid + j*256; cp16(dst + 16384 + idx*16, b + idx*16); }
    };

    const uint32_t axor = (uint32_t)(g*16);
    uint32_t aoff[2][2], boff[8];
    #pragma unroll
    for (int im=0;im<2;im++){
        aoff[im][0] = (uint32_t)((wm + im*16 + g    )*128);
        aoff[im][1] = (uint32_t)((wm + im*16 + g + 8)*128);
    }
    #pragma unroll
    for (int in=0;in<8;in++) boff[in] = (uint32_t)((wn + in*8 + g)*128);

    float c[2][8][4];
    #pragma unroll
    for (int im=0;im<2;im++)
        #pragma unroll
        for (int in=0;in<8;in++)
            #pragma unroll
            for (int r=0;r<4;r++) c[im][in][r]=0.0f;

    uint32_t aF[2][2][4], bF[2][8][2];
    auto ldA = [&](const char* Ac, int ck, uint32_t (&a)[2][4]){
        uint32_t ko = (uint32_t)(ck*32 + t*8) ^ axor;
        #pragma unroll
        for (int im=0;im<2;im++){
            uint2 v0 = *(const uint2*)(Ac + aoff[im][0] + ko);   // rows g / g+8
            uint2 v1 = *(const uint2*)(Ac + aoff[im][1] + ko);
            a[im][0]=v0.x; a[im][2]=v0.y;   // k 2t..2t+1 | 2t+8..2t+9
            a[im][1]=v1.x; a[im][3]=v1.y;
        }
    };
    auto ldB = [&](const char* Bc, int ck, uint32_t (&b)[8][2]){
        uint32_t ko = (uint32_t)(ck*32 + t*8) ^ axor;
        #pragma unroll
        for (int in=0;in<8;in++){
            uint2 v = *(const uint2*)(Bc + boff[in] + ko);
            b[in][0]=v.x; b[in][1]=v.y;
        }
    };

    loadStage(0,0); asm volatile("cp.async.commit_group;\n");
    loadStage(1,1); asm volatile("cp.async.commit_group;\n");

    #pragma unroll 1
    for (int s=0; s<KT; s++){
        asm volatile("cp.async.wait_group 1;\n");
        __syncthreads();
        if (s+2 < KT) loadStage((s+2)%3, s+2);
        asm volatile("cp.async.commit_group;\n");   // always commit -> exact accounting

        const char* Ac = (const char*)sm + (s%3)*STG_B;
        const char* Bc = Ac + 16384;

        ldA(Ac, 0, aF[0]); ldB(Bc, 0, bF[0]);
        #pragma unroll
        for (int ck=0; ck<4; ck++){
            if (ck < 3){ ldA(Ac, ck+1, aF[(ck+1)&1]); ldB(Bc, ck+1, bF[(ck+1)&1]); }
            uint32_t (&a)[2][4] = aF[ck&1];
            uint32_t (&b)[8][2] = bF[ck&1];
            #pragma unroll
            for (int im=0;im<2;im++)
                #pragma unroll
                for (int in=0;in<8;in++){
                    asm volatile(
                        "mma.sync.aligned.m16n8k16.row.col.f32.f16.f16.f32 "
                        "{%0,%1,%2,%3}, {%4,%5,%6,%7}, {%8,%9}, {%0,%1,%2,%3};"
                        : "+f"(c[im][in][0]), "+f"(c[im][in][1]),
                          "+f"(c[im][in][2]), "+f"(c[im][in][3])
                        : "r"(a[im][0]), "r"(a[im][1]), "r"(a[im][2]), "r"(a[im][3]),
                          "r"(b[in][0]), "r"(b[in][1]));
                }
        }
    }
    asm volatile("cp.async.wait_group 0;\n");

    if (G1){
        // stage bias+gelu through smem, emit hidden as fp16 pair-packed panels
        __half* Out = (__half*)OutV;
        __syncthreads();
        float* stage = sm;                  // [128][132]
        #pragma unroll
        for (int im=0;im<2;im++)
            #pragma unroll
            for (int rh=0;rh<2;rh++){
                int row = wm + im*16 + g + rh*8;
                #pragma unroll
                for (int in=0;in<8;in++){
                    int col = wn + in*8 + 2*t;
                    float v0 = c[im][in][rh*2+0] + __ldg(&bias[bx*BN+col]);
                    float v1 = c[im][in][rh*2+1] + __ldg(&bias[bx*BN+col+1]);
                    v0 = gelu_exact(v0);
                    v1 = gelu_exact(v1);
                    *(float2*)&stage[row*132 + col] = make_float2(v0, v1);
                }
            }
        __syncthreads();
        // pack 128 rows x 128 n -> 2 k-blocks of 64 (k-dim of GEMM2)
        const int KT2 = HID/64;
        #pragma unroll
        for (int i=0;i<16;i++){
            int p = tid + i*256;            // 4096 pairs
            int m = p>>5, r = p&31;
            int kbl = r>>4, j = r&15;
            int k0 = kbl*64 + (j>>2)*16 + (j&3)*2;
            uint2 v = make_uint2(h2u(stage[m*132+k0],   stage[m*132+k0+1]),
                                 h2u(stage[m*132+k0+8], stage[m*132+k0+9]));
            char* panel = (char*)(Out + (((size_t)e*16 + by)*KT2 + (bx*2 + kbl))*(size_t)PANELH);
            uint32_t off = (uint32_t)(m*128 + j*8) ^ (uint32_t)((m&7)*16);
            *(uint2*)(panel + off) = v;
        }
    } else {
        float* Out = (float*)OutV;
        const int Nout = NB*BN;
        #pragma unroll
        for (int im=0;im<2;im++)
            #pragma unroll
            for (int rh=0;rh<2;rh++){
                int row = by*BM + wm + im*16 + g + rh*8;
                #pragma unroll
                for (int in=0;in<8;in++){
                    int col = bx*BN + wn + in*8 + 2*t;
                    float v0 = c[im][in][rh*2+0] + __ldg(&bias[col]);
                    float v1 = c[im][in][rh*2+1] + __ldg(&bias[col+1]);
                    *reinterpret_cast<float2*>(&Out[((size_t)e*MTOK + row)*Nout + col]) =
                        make_float2(v0, v1);
                }
            }
    }
}

// ---------------- host ----------------
extern "C" void kernel_launch(void* const* d_in, const int* in_sizes, int n_in,
                              void* d_out, int out_size)
{
    const float* x  = (const float*)d_in[0];   // [E, 2048, 1024]
    const float* w1 = (const float*)d_in[1];   // [E, 1024, 4096]
    const float* w2 = (const float*)d_in[2];   // [E, 4096, 1024]
    const float* b1 = (const float*)d_in[3];   // [4096]
    const float* b2 = (const float*)d_in[4];   // [1024]
    float* out = (float*)d_out;                // [E, 2048, 1024]

    __half *xp, *w1p, *w2p, *hid;
    cudaGetSymbolAddress((void**)&xp,  g_xp);
    cudaGetSymbolAddress((void**)&w1p, g_w1p);
    cudaGetSymbolAddress((void**)&w2p, g_w2p);
    cudaGetSymbolAddress((void**)&hid, g_hid);

    cudaFuncSetAttribute(gemm_t<true>,  cudaFuncAttributeMaxDynamicSharedMemorySize, SMEM_BYTES);
    cudaFuncSetAttribute(gemm_t<false>, cudaFuncAttributeMaxDynamicSharedMemorySize, SMEM_BYTES);

    // pre-pass: fp16 conversion + panelization
    pack_x<<<dim3(DIM/64, MTOK/128, EXPERTS), 256>>>(x, xp);
    pack_w<<<dim3(HID/128, DIM/64, EXPERTS), 256>>>(w1, w1p, DIM, HID);
    pack_w<<<dim3(DIM/128, HID/64, EXPERTS), 256>>>(w2, w2p, HID, DIM);

    // GEMM1 + exact GELU -> hidden fp16 panels; GEMM2 -> row-major fp32 out
    gemm_t<true ><<<dim3(HID/BN, MTOK/BM, EXPERTS), 256, SMEM_BYTES>>>(xp, w1p, b1, hid, DIM/64);
    gemm_t<false><<<dim3(DIM/BN, MTOK/BM, EXPERTS), 256, SMEM_BYTES>>>(hid, w2p, b2, out, HID/64);
}

// round 8
// speedup vs baseline: 2.3695x; 1.2824x over previous
#include <cuda_runtime.h>
#include <cuda_fp16.h>
#include <cstdint>

// Problem shape (fixed)
#define EXPERTS 16
#define MTOK    2048
#define DIM     1024
#define HID     4096

// GEMM tiling
#define BM 128
#define BN 128
#define BK 64                            // fp16: 64 k per 16KB panel (128B rows)
#define PANELH 8192                      // halfs per 128x64 panel (16KB)
#define STG_B  (2*PANELH*2)              // A + B panel bytes per stage (32KB)
#define SMEM_BYTES (3*STG_B)             // 98304 -> 2 CTAs/SM

// Scratch (allocation-free rule: __device__ globals)
__device__ __half g_xp [(size_t)EXPERTS*MTOK*DIM];   // x panels    [e][mb=16][kb=16]
__device__ __half g_w1p[(size_t)EXPERTS*DIM*HID];    // w1^T panels [e][nb=32][kb=16]
__device__ __half g_w2p[(size_t)EXPERTS*HID*DIM];    // w2^T panels [e][nb=8][kb=64]
__device__ __half g_hid[(size_t)EXPERTS*MTOK*HID];   // hidden panels [e][mb=16][kb=64]

// Panel layout (A and B identical): 128 rows x 64 k fp16, 128B per row.
// Row r, 16B group h (k = 8h..8h+7, linear) at byte  r*128 + ((h ^ (r&7))<<4).

// ---------------- helpers ----------------
__device__ __forceinline__ float gelu_exact(float x){
    return 0.5f*x*(1.0f+erff(x*0.70710678118654752440f));
}
__device__ __forceinline__ void cp16(void* smem, const void* gmem){
    unsigned s = (unsigned)__cvta_generic_to_shared(smem);
    asm volatile("cp.async.cg.shared.global [%0], [%1], 16;\n" :: "r"(s), "l"(gmem));
}
__device__ __forceinline__ uint32_t h2u(float a, float b){
    __half2 h = __floats2half2_rn(a, b);
    return *reinterpret_cast<uint32_t*>(&h);
}
__device__ __forceinline__ void ldsm4(uint32_t (&r)[4], uint32_t addr){
    asm volatile("ldmatrix.sync.aligned.m8n8.x4.shared.b16 {%0,%1,%2,%3}, [%4];"
        : "=r"(r[0]), "=r"(r[1]), "=r"(r[2]), "=r"(r[3]) : "r"(addr));
}

// ---------------- pre-pass: x -> fp16 linear-group panels ----------------
__global__ __launch_bounds__(256) void pack_x(const float* __restrict__ X, __half* __restrict__ P){
    const int e = blockIdx.z, mb = blockIdx.y, kb = blockIdx.x;   // 128 rows x 64 k
    char* panel = (char*)(P + (((size_t)e*16 + mb)*(DIM/64) + kb)*(size_t)PANELH);
    #pragma unroll
    for (int i=0;i<4;i++){
        int idx = threadIdx.x + i*256;     // 1024 groups
        int m = idx>>3, h = idx&7;
        const float* s = X + ((size_t)e*MTOK + (size_t)mb*128 + m)*DIM + kb*64 + h*8;
        float4 v0 = *(const float4*)s;
        float4 v1 = *(const float4*)(s+4);
        uint4 o = make_uint4(h2u(v0.x,v0.y), h2u(v0.z,v0.w),
                             h2u(v1.x,v1.y), h2u(v1.z,v1.w));
        uint32_t off = (uint32_t)(m*128) + (uint32_t)((h ^ (m&7))<<4);
        *(uint4*)(panel + off) = o;
    }
}

// ---- pre-pass: W[K,N] -> fp16 W^T linear-group panels [e][nb][kb] ----
__global__ __launch_bounds__(256) void pack_w(const float* __restrict__ W, __half* __restrict__ P,
                                              int K, int N){
    __shared__ float ts[64][132];
    const int e = blockIdx.z, nb = blockIdx.x, kb = blockIdx.y;   // 64 k x 128 n
    const float* src = W + ((size_t)e*K + (size_t)kb*64)*N + (size_t)nb*128;
    #pragma unroll
    for (int i=0;i<8;i++){
        int idx = threadIdx.x + i*256;     // 2048 float4
        int r = idx>>5, c4 = idx&31;
        float4 v = *(const float4*)(src + (size_t)r*N + c4*4);
        ts[r][c4*4+0]=v.x; ts[r][c4*4+1]=v.y; ts[r][c4*4+2]=v.z; ts[r][c4*4+3]=v.w;
    }
    __syncthreads();
    char* panel = (char*)(P + (((size_t)e*(N>>7) + nb)*(size_t)(K>>6) + kb)*(size_t)PANELH);
    #pragma unroll
    for (int i=0;i<4;i++){
        int idx = threadIdx.x + i*256;     // 1024 groups
        int n = idx>>3, h = idx&7;
        float f[8];
        #pragma unroll
        for (int j=0;j<8;j++) f[j] = ts[h*8+j][n];
        uint4 o = make_uint4(h2u(f[0],f[1]), h2u(f[2],f[3]),
                             h2u(f[4],f[5]), h2u(f[6],f[7]));
        uint32_t off = (uint32_t)(n*128) + (uint32_t)((h ^ (n&7))<<4);
        *(uint4*)(panel + off) = o;
    }
}

// ---------------- main GEMM: mma.sync fp16 m16n8k16, ldmatrix frags ----------------
template<bool G1>
__global__ void __launch_bounds__(256,2)
gemm_t(const __half* __restrict__ Ap, const __half* __restrict__ Bp,
       const float* __restrict__ bias, void* __restrict__ OutV, int KT)
{
    extern __shared__ float sm[];
    const uint32_t smemBase = (uint32_t)__cvta_generic_to_shared(sm);
    const int tid = threadIdx.x, warp = tid>>5, lane = tid&31;
    const int g = lane>>2, t = lane&3;
    const int lan7 = lane&7;
    const int wm = (warp&3)*32, wn = (warp>>2)*64;
    const int bx = blockIdx.x, by = blockIdx.y, e = blockIdx.z;
    const int NB = gridDim.x;

    const __half* Ab0 = Ap + ((size_t)e*gridDim.y + by)*(size_t)KT*PANELH;
    const __half* Bb0 = Bp + ((size_t)e*NB + bx)*(size_t)KT*PANELH;

    auto loadStage = [&](int slot, int s){
        char* dst = (char*)sm + slot*STG_B;
        const char* a = (const char*)(Ab0 + (size_t)s*PANELH);
        const char* b = (const char*)(Bb0 + (size_t)s*PANELH);
        #pragma unroll
        for (int j=0;j<4;j++){ int idx = tid + j*256; cp16(dst + idx*16, a + idx*16); }
        #pragma unroll
        for (int j=0;j<4;j++){ int idx = tid + j*256; cp16(dst + 16384 + idx*16, b + idx*16); }
    };

    // ldmatrix per-thread row byte offsets (within panel)
    // A (x4): m0 rows+0-7 k+0 | m1 rows+8-15 k+0 | m2 rows+0-7 k+8 | m3 rows+8-15 k+8
    const int kselA = (lane>>4)&1;
    uint32_t aRow[2];
    #pragma unroll
    for (int im=0;im<2;im++)
        aRow[im] = (uint32_t)((wm + im*16 + lan7 + ((lane>>3)&1)*8) * 128);
    // B (x4, pair p covers in=2p,2p+1): m0 in=2p k+0 | m1 in=2p k+8 | m2 in=2p+1 k+0 | m3 in=2p+1 k+8
    const int kselB = (lane>>3)&1;
    const uint32_t bRow0 = (uint32_t)((wn + lan7 + ((lane>>4)&1)*8) * 128);

    float c[2][8][4];
    #pragma unroll
    for (int im=0;im<2;im++)
        #pragma unroll
        for (int in=0;in<8;in++)
            #pragma unroll
            for (int r=0;r<4;r++) c[im][in][r]=0.0f;

    loadStage(0,0); asm volatile("cp.async.commit_group;\n");
    loadStage(1,1); asm volatile("cp.async.commit_group;\n");

    #pragma unroll 1
    for (int s=0; s<KT; s++){
        asm volatile("cp.async.wait_group 1;\n");
        __syncthreads();
        if (s+2 < KT) loadStage((s+2)%3, s+2);
        asm volatile("cp.async.commit_group;\n");   // always commit -> exact accounting

        const uint32_t Ab = smemBase + (s%3)*STG_B;
        const uint32_t Bb = Ab + 16384;

        #pragma unroll
        for (int ck=0; ck<4; ck++){
            const uint32_t gA = (uint32_t)(((ck*2 + kselA) ^ lan7) << 4);
            const uint32_t gB = (uint32_t)(((ck*2 + kselB) ^ lan7) << 4);
            uint32_t a[2][4], bq[4][4];
            ldsm4(a[0], Ab + aRow[0] + gA);
            ldsm4(a[1], Ab + aRow[1] + gA);
            #pragma unroll
            for (int p=0;p<4;p++)
                ldsm4(bq[p], Bb + bRow0 + (uint32_t)(p*2048) + gB);
            #pragma unroll
            for (int im=0;im<2;im++)
                #pragma unroll
                for (int in=0;in<8;in++){
                    const uint32_t b0 = bq[in>>1][(in&1)*2];
                    const uint32_t b1 = bq[in>>1][(in&1)*2+1];
                    asm volatile(
                        "mma.sync.aligned.m16n8k16.row.col.f32.f16.f16.f32 "
                        "{%0,%1,%2,%3}, {%4,%5,%6,%7}, {%8,%9}, {%0,%1,%2,%3};"
                        : "+f"(c[im][in][0]), "+f"(c[im][in][1]),
                          "+f"(c[im][in][2]), "+f"(c[im][in][3])
                        : "r"(a[im][0]), "r"(a[im][1]), "r"(a[im][2]), "r"(a[im][3]),
                          "r"(b0), "r"(b1));
                }
        }
    }
    asm volatile("cp.async.wait_group 0;\n");

    if (G1){
        // stage bias+gelu through smem, emit hidden as fp16 linear-group panels
        __half* Out = (__half*)OutV;
        __syncthreads();
        float* stage = sm;                  // [128][132]
        #pragma unroll
        for (int im=0;im<2;im++)
            #pragma unroll
            for (int rh=0;rh<2;rh++){
                int row = wm + im*16 + g + rh*8;
                #pragma unroll
                for (int in=0;in<8;in++){
                    int col = wn + in*8 + 2*t;
                    float v0 = c[im][in][rh*2+0] + __ldg(&bias[bx*BN+col]);
                    float v1 = c[im][in][rh*2+1] + __ldg(&bias[bx*BN+col+1]);
                    v0 = gelu_exact(v0);
                    v1 = gelu_exact(v1);
                    *(float2*)&stage[row*132 + col] = make_float2(v0, v1);
                }
            }
        __syncthreads();
        // pack 128 rows x 128 n -> 2 k-blocks of 64 (k-dim of GEMM2)
        const int KT2 = HID/64;
        #pragma unroll
        for (int i=0;i<8;i++){
            int p = tid + i*256;            // 2048 groups
            int m = p>>4, r = p&15;
            int kbl = r>>3, h = r&7;
            const float* srow = &stage[m*132 + kbl*64 + h*8];
            uint4 v = make_uint4(h2u(srow[0],srow[1]), h2u(srow[2],srow[3]),
                                 h2u(srow[4],srow[5]), h2u(srow[6],srow[7]));
            char* panel = (char*)(Out + (((size_t)e*16 + by)*KT2 + (bx*2 + kbl))*(size_t)PANELH);
            uint32_t off = (uint32_t)(m*128) + (uint32_t)((h ^ (m&7))<<4);
            *(uint4*)(panel + off) = v;
        }
    } else {
        float* Out = (float*)OutV;
        const int Nout = NB*BN;
        #pragma unroll
        for (int im=0;im<2;im++)
            #pragma unroll
            for (int rh=0;rh<2;rh++){
                int row = by*BM + wm + im*16 + g + rh*8;
                #pragma unroll
                for (int in=0;in<8;in++){
                    int col = bx*BN + wn + in*8 + 2*t;
                    float v0 = c[im][in][rh*2+0] + __ldg(&bias[col]);
                    float v1 = c[im][in][rh*2+1] + __ldg(&bias[col+1]);
                    *reinterpret_cast<float2*>(&Out[((size_t)e*MTOK + row)*Nout + col]) =
                        make_float2(v0, v1);
                }
            }
    }
}

// ---------------- host ----------------
extern "C" void kernel_launch(void* const* d_in, const int* in_sizes, int n_in,
                              void* d_out, int out_size)
{
    const float* x  = (const float*)d_in[0];   // [E, 2048, 1024]
    const float* w1 = (const float*)d_in[1];   // [E, 1024, 4096]
    const float* w2 = (const float*)d_in[2];   // [E, 4096, 1024]
    const float* b1 = (const float*)d_in[3];   // [4096]
    const float* b2 = (const float*)d_in[4];   // [1024]
    float* out = (float*)d_out;                // [E, 2048, 1024]

    __half *xp, *w1p, *w2p, *hid;
    cudaGetSymbolAddress((void**)&xp,  g_xp);
    cudaGetSymbolAddress((void**)&w1p, g_w1p);
    cudaGetSymbolAddress((void**)&w2p, g_w2p);
    cudaGetSymbolAddress((void**)&hid, g_hid);

    cudaFuncSetAttribute(gemm_t<true>,  cudaFuncAttributeMaxDynamicSharedMemorySize, SMEM_BYTES);
    cudaFuncSetAttribute(gemm_t<false>, cudaFuncAttributeMaxDynamicSharedMemorySize, SMEM_BYTES);

    // pre-pass: fp16 conversion + panelization
    pack_x<<<dim3(DIM/64, MTOK/128, EXPERTS), 256>>>(x, xp);
    pack_w<<<dim3(HID/128, DIM/64, EXPERTS), 256>>>(w1, w1p, DIM, HID);
    pack_w<<<dim3(DIM/128, HID/64, EXPERTS), 256>>>(w2, w2p, HID, DIM);

    // GEMM1 + exact GELU -> hidden fp16 panels; GEMM2 -> row-major fp32 out
    gemm_t<true ><<<dim3(HID/BN, MTOK/BM, EXPERTS), 256, SMEM_BYTES>>>(xp, w1p, b1, hid, DIM/64);
    gemm_t<false><<<dim3(DIM/BN, MTOK/BM, EXPERTS), 256, SMEM_BYTES>>>(hid, w2p, b2, out, HID/64);
}